// round 13
// baseline (speedup 1.0000x reference)
#include <cuda_runtime.h>
#include <cuda_bf16.h>

// CrossHeadOnlineHadamardHook: 32-point Walsh-Hadamard across heads.
// x: (T, 4096) fp32 rows, T = 16384. heads = 32, HEAD_DIM = 128.
// For each (t, d): v[h] = x[t*4096 + h*128 + d], v = H32 * v / sqrt(32).
//
// R12 probe: identical to the measured-best R6 kernel (82.08us,
// 6.22 TB/s) except stores use write-through (__stwt) instead of
// streaming (__stcs). Hypothesis: pushing writes straight through L2
// (instead of leaving dirty lines for allocator-scheduled writeback)
// smooths the read/write interleave at the DRAM controller. If this is
// neutral, the kernel is final at the chip's mixed R/W HBM ceiling.
//
// Config notes (all measured): 128-thread blocks are load-bearing
// (154 regs -> 3 CTAs/SM = 12 warps; 256-thr drops to 8 warps, -9% BW).
// Ruled out: smem phase-split (-12%), persistent grid (-10%), f2/f4 and
// cache-policy variants (neutral at the same 6.23 TB/s ceiling).

#define NUM_HEADS 32
#define HEAD_DIM  128
#define HIDDEN    (NUM_HEADS * HEAD_DIM)      // 4096
#define QUADS_PER_ROW (HIDDEN / 4)            // 1024 float4 per token row
#define HQUAD_STRIDE (HEAD_DIM / 4)           // 32 float4 between heads
#define THREADS 128

__global__ __launch_bounds__(THREADS)
void had32_crosshead_f4_kernel(const float4* __restrict__ x,
                               float4* __restrict__ out,
                               int n_items_total)
{
    int item = blockIdx.x * THREADS + threadIdx.x;
    if (item >= n_items_total) return;

    int t = item >> 5;          // token index (32 quads per token)
    int q = item & 31;          // which float4 within the head dim

    size_t base = (size_t)t * QUADS_PER_ROW + q;
    const float4* __restrict__ px = x + base;
    float4*       __restrict__ py = out + base;

    float4 v[NUM_HEADS];

    // 32 coalesced LDG.128 (512B/warp), evict-first streaming
#pragma unroll
    for (int h = 0; h < NUM_HEADS; ++h) {
        v[h] = __ldcs(px + (size_t)h * HQUAD_STRIDE);
    }

    // In-register 32-point FWHT over 4 independent lanes
#pragma unroll
    for (int s = 1; s < NUM_HEADS; s <<= 1) {
#pragma unroll
        for (int i = 0; i < NUM_HEADS; ++i) {
            if ((i & s) == 0) {
                float4 a = v[i];
                float4 b = v[i + s];
                v[i].x     = a.x + b.x;
                v[i].y     = a.y + b.y;
                v[i].z     = a.z + b.z;
                v[i].w     = a.w + b.w;
                v[i + s].x = a.x - b.x;
                v[i + s].y = a.y - b.y;
                v[i + s].z = a.z - b.z;
                v[i + s].w = a.w - b.w;
            }
        }
    }

    const float scl = 0.17677669529663687f;   // 1/sqrt(32)

    // 32 coalesced STG.128, write-through (probe: smooth write stream
    // to DRAM instead of allocator-scheduled dirty writeback)
#pragma unroll
    for (int h = 0; h < NUM_HEADS; ++h) {
        float4 r;
        r.x = v[h].x * scl;
        r.y = v[h].y * scl;
        r.z = v[h].z * scl;
        r.w = v[h].w * scl;
        __stwt(py + (size_t)h * HQUAD_STRIDE, r);
    }
}

extern "C" void kernel_launch(void* const* d_in, const int* in_sizes, int n_in,
                              void* d_out, int out_size)
{
    const float4* x = (const float4*)d_in[0];
    float4* out = (float4*)d_out;

    int n = in_sizes[0];                 // total fp32 elements (4*4096*4096)
    int n_items = n >> 7;                // one item = quad x 32 heads = 128 floats
    int blocks = (n_items + THREADS - 1) / THREADS;

    had32_crosshead_f4_kernel<<<blocks, THREADS>>>(x, out, n_items);
}

// round 14
// speedup vs baseline: 1.0215x; 1.0215x over previous
#include <cuda_runtime.h>
#include <cuda_bf16.h>

// CrossHeadOnlineHadamardHook: 32-point Walsh-Hadamard across heads.
// x: (T, 4096) fp32 rows, T = 16384. heads = 32, HEAD_DIM = 128.
// For each (t, d): v[h] = x[t*4096 + h*128 + d], v = H32 * v / sqrt(32).
//
// FINAL KERNEL — measured best across 8 variants (82.08-82.11us,
// 6.22-6.26 TB/s HBM = this chip's mixed read+write ceiling; 536 MB
// traffic is irreducible for an out-of-place transform).
//
// Structure: one thread owns one (token, d-quad).
//   - 32 front-batched coalesced LDG.128 (512B/warp, 16KB burst/warp),
//     evict-first (__ldcs) — data is read-once.
//   - In-register 32-point FWHT over 4 independent fp32 lanes
//     (natural-order Sylvester H32; stage order irrelevant). rel_err 0.0.
//   - 32 coalesced STG.128, evict-first (__stcs) — data is write-once.
//
// Config is load-bearing (all alternatives measured):
//   - 128-thread blocks: 154 regs x 128 thr -> 3 CTAs/SM = 12 warps,
//     the minimum that saturates DRAM queues. 256-thr -> 1 CTA/SM -> -9%.
//   - Non-persistent grid (4096 CTAs): hardware wave scheduling overlaps
//     CTA prologues for free; grid-stride looping serializes per-warp
//     load batches behind stores -> -10%.
//   - Continuous mixed R/W beats phase-split smem staging (-12%).
//   - __stwt write-through stores: -2%. __stcs is correct choice.

#define NUM_HEADS 32
#define HEAD_DIM  128
#define HIDDEN    (NUM_HEADS * HEAD_DIM)      // 4096
#define QUADS_PER_ROW (HIDDEN / 4)            // 1024 float4 per token row
#define HQUAD_STRIDE (HEAD_DIM / 4)           // 32 float4 between heads
#define THREADS 128

__global__ __launch_bounds__(THREADS)
void had32_crosshead_f4_kernel(const float4* __restrict__ x,
                               float4* __restrict__ out,
                               int n_items_total)
{
    int item = blockIdx.x * THREADS + threadIdx.x;
    if (item >= n_items_total) return;

    int t = item >> 5;          // token index (32 quads per token)
    int q = item & 31;          // which float4 within the head dim

    size_t base = (size_t)t * QUADS_PER_ROW + q;
    const float4* __restrict__ px = x + base;
    float4*       __restrict__ py = out + base;

    float4 v[NUM_HEADS];

    // 32 coalesced LDG.128 (512B/warp), evict-first streaming
#pragma unroll
    for (int h = 0; h < NUM_HEADS; ++h) {
        v[h] = __ldcs(px + (size_t)h * HQUAD_STRIDE);
    }

    // In-register 32-point FWHT over 4 independent lanes
#pragma unroll
    for (int s = 1; s < NUM_HEADS; s <<= 1) {
#pragma unroll
        for (int i = 0; i < NUM_HEADS; ++i) {
            if ((i & s) == 0) {
                float4 a = v[i];
                float4 b = v[i + s];
                v[i].x     = a.x + b.x;
                v[i].y     = a.y + b.y;
                v[i].z     = a.z + b.z;
                v[i].w     = a.w + b.w;
                v[i + s].x = a.x - b.x;
                v[i + s].y = a.y - b.y;
                v[i + s].z = a.z - b.z;
                v[i + s].w = a.w - b.w;
            }
        }
    }

    const float scl = 0.17677669529663687f;   // 1/sqrt(32)

    // 32 coalesced STG.128, evict-first
#pragma unroll
    for (int h = 0; h < NUM_HEADS; ++h) {
        float4 r;
        r.x = v[h].x * scl;
        r.y = v[h].y * scl;
        r.z = v[h].z * scl;
        r.w = v[h].w * scl;
        __stcs(py + (size_t)h * HQUAD_STRIDE, r);
    }
}

extern "C" void kernel_launch(void* const* d_in, const int* in_sizes, int n_in,
                              void* d_out, int out_size)
{
    const float4* x = (const float4*)d_in[0];
    float4* out = (float4*)d_out;

    int n = in_sizes[0];                 // total fp32 elements (4*4096*4096)
    int n_items = n >> 7;                // one item = quad x 32 heads = 128 floats
    int blocks = (n_items + THREADS - 1) / THREADS;

    had32_crosshead_f4_kernel<<<blocks, THREADS>>>(x, out, n_items);
}